// round 8
// baseline (speedup 1.0000x reference)
#include <cuda_runtime.h>
#include <cstdint>

#define NC     16      // clusters
#define CS     32      // cluster size
#define NH     16      // hidden
#define NF     512     // features = NC*CS
#define BATCH  131072
#define RROWS  64      // rows per block tile
#define THREADS 512
#define TSTRIDE 516    // padded row stride (floats)

// Fused per-cluster weights: W[n][c][k] = sum_h dec_w[n][c][h]*enc_w[n][h][k]
__device__ float g_W[NC * CS * CS];
__device__ float g_bias[NC * CS];
__device__ int   g_pos[NF];   // pos[feature] = n*32+k  (inverse of clusters perm)

__global__ void prep_kernel(const float* __restrict__ enc_w,
                            const float* __restrict__ enc_b,
                            const float* __restrict__ dec_w,
                            const float* __restrict__ dec_b,
                            const int*   __restrict__ clusters) {
    int t = blockIdx.x * blockDim.x + threadIdx.x;
    if (t < NC * CS * CS) {
        int n = t >> 10;
        int c = (t >> 5) & 31;
        int k = t & 31;
        const float* dw = dec_w + (n * CS + c) * NH;
        const float* ew = enc_w + n * NH * CS + k;
        float s = 0.f;
#pragma unroll
        for (int h = 0; h < NH; h++) s += dw[h] * ew[h * CS];
        g_W[t] = s;
    }
    if (t < NC * CS) {
        int n = t >> 5;
        const float* dw = dec_w + t * NH;
        const float* eb = enc_b + n * NH;
        float s = dec_b[t];
#pragma unroll
        for (int h = 0; h < NH; h++) s += dw[h] * eb[h];
        g_bias[t] = s;
        g_pos[clusters[t]] = t;
    }
}

// 512 threads = 16 warps = 16 clusters. Lane = rh*16 + kh*8 + q:
//   rh = row-in-pair (2 rows per step), kh = k-half, q = output quad.
// Each lane: W[cl][4q..4q+3][kh*16..kh*16+15] register-stationary (64 regs),
// partial k-sums, shfl.xor(8) butterfly completes the dot product.
__global__ void __launch_bounds__(THREADS, 1)
ensemble_kernel(const float* __restrict__ x, float* __restrict__ y) {
    extern __shared__ __align__(16) float tile[];   // RROWS * TSTRIDE floats

    const int tid  = threadIdx.x;
    const int warp = tid >> 5;       // cluster 0..15
    const int lane = tid & 31;
    const int rh   = lane >> 4;      // 0..1 row in pair
    const int kh   = (lane >> 3) & 1;// 0..1 k-half
    const int q    = lane & 7;       // 0..7 output quad
    const int cl   = warp;
    const long long row0 = (long long)blockIdx.x * RROWS;

    // ---- load phase: coalesced global read, permuted scatter into smem ----
    {
        const float4* xv = (const float4*)(x) + row0 * (NF / 4);
        const int4*   pv = (const int4*)g_pos;
#pragma unroll 4
        for (int i = 0; i < (RROWS * NF / 4) / THREADS; i++) {
            int idx = tid + i * THREADS;  // float4 index within tile
            int r   = idx >> 7;           // 128 float4 per row
            int f4  = idx & 127;
            float4 v = xv[idx];
            int4   p = pv[f4];
            float* dst = tile + r * TSTRIDE;
            dst[p.x] = v.x;
            dst[p.y] = v.y;
            dst[p.z] = v.z;
            dst[p.w] = v.w;
        }
    }

    // ---- weights: 4 output rows x 16 k (this lane's k-half), rotated by q ----
    // chunk index for step j: ch = kh*4 + ((q+j)&3); k = ch*4 .. ch*4+3
    unsigned long long w[4][8];
#pragma unroll
    for (int o = 0; o < 4; o++) {
        const float* wr = g_W + (cl * CS + 4 * q + o) * CS;
#pragma unroll
        for (int j = 0; j < 4; j++) {
            int ch = kh * 4 + ((q + j) & 3);
            ulonglong2 v = *(const ulonglong2*)(wr + ch * 4);
            w[o][2 * j]     = v.x;
            w[o][2 * j + 1] = v.y;
        }
    }
    const float4 bias = *(const float4*)(g_bias + cl * CS + 4 * q);

    __syncthreads();

    uint32_t sb;
    asm("{ .reg .u64 t0; cvta.to.shared.u64 t0, %1; cvt.u32.u64 %0, t0; }"
        : "=r"(sb) : "l"(tile));

    // lane's fixed compute-phase offsets
    const uint32_t seg = (uint32_t)(cl * CS * 4);           // cluster segment bytes
    float* ybase = y + row0 * NF + cl * CS + q * 4 + kh * 2;

#pragma unroll 2
    for (int it = 0; it < RROWS / 2; it++) {
        const int row = it * 2 + rh;
        const uint32_t base = sb + (uint32_t)(row * TSTRIDE * 4) + seg;

        unsigned long long a0, a1, a2, a3;
#pragma unroll
        for (int j = 0; j < 4; j++) {
            unsigned long long x0, x1;
            uint32_t addr = base + (uint32_t)((kh * 4 + ((q + j) & 3)) << 4);
            asm volatile("ld.shared.v2.u64 {%0,%1},[%2];"
                         : "=l"(x0), "=l"(x1) : "r"(addr));
            if (j == 0) {
                asm("mul.rn.f32x2 %0,%1,%2;" : "=l"(a0) : "l"(w[0][0]), "l"(x0));
                asm("mul.rn.f32x2 %0,%1,%2;" : "=l"(a1) : "l"(w[1][0]), "l"(x0));
                asm("mul.rn.f32x2 %0,%1,%2;" : "=l"(a2) : "l"(w[2][0]), "l"(x0));
                asm("mul.rn.f32x2 %0,%1,%2;" : "=l"(a3) : "l"(w[3][0]), "l"(x0));
            } else {
                asm("fma.rn.f32x2 %0,%1,%2,%0;" : "+l"(a0) : "l"(w[0][2 * j]), "l"(x0));
                asm("fma.rn.f32x2 %0,%1,%2,%0;" : "+l"(a1) : "l"(w[1][2 * j]), "l"(x0));
                asm("fma.rn.f32x2 %0,%1,%2,%0;" : "+l"(a2) : "l"(w[2][2 * j]), "l"(x0));
                asm("fma.rn.f32x2 %0,%1,%2,%0;" : "+l"(a3) : "l"(w[3][2 * j]), "l"(x0));
            }
            asm("fma.rn.f32x2 %0,%1,%2,%0;" : "+l"(a0) : "l"(w[0][2 * j + 1]), "l"(x1));
            asm("fma.rn.f32x2 %0,%1,%2,%0;" : "+l"(a1) : "l"(w[1][2 * j + 1]), "l"(x1));
            asm("fma.rn.f32x2 %0,%1,%2,%0;" : "+l"(a2) : "l"(w[2][2 * j + 1]), "l"(x1));
            asm("fma.rn.f32x2 %0,%1,%2,%0;" : "+l"(a3) : "l"(w[3][2 * j + 1]), "l"(x1));
        }

        // fold packed halves, butterfly across k-half lanes (xor 8)
        uint32_t lo, hi;
        float s0, s1, s2, s3;
        asm("mov.b64 {%0,%1},%2;" : "=r"(lo), "=r"(hi) : "l"(a0));
        s0 = __uint_as_float(lo) + __uint_as_float(hi);
        asm("mov.b64 {%0,%1},%2;" : "=r"(lo), "=r"(hi) : "l"(a1));
        s1 = __uint_as_float(lo) + __uint_as_float(hi);
        asm("mov.b64 {%0,%1},%2;" : "=r"(lo), "=r"(hi) : "l"(a2));
        s2 = __uint_as_float(lo) + __uint_as_float(hi);
        asm("mov.b64 {%0,%1},%2;" : "=r"(lo), "=r"(hi) : "l"(a3));
        s3 = __uint_as_float(lo) + __uint_as_float(hi);

        s0 += __shfl_xor_sync(0xffffffffu, s0, 8);
        s1 += __shfl_xor_sync(0xffffffffu, s1, 8);
        s2 += __shfl_xor_sync(0xffffffffu, s2, 8);
        s3 += __shfl_xor_sync(0xffffffffu, s3, 8);

        // every lane now has all 4 outputs; kh selects which pair it stores
        float2 out;
        if (kh == 0) { out.x = s0 + bias.x; out.y = s1 + bias.y; }
        else         { out.x = s2 + bias.z; out.y = s3 + bias.w; }
        *(float2*)(ybase + (size_t)row * NF) = out;
    }
}

extern "C" void kernel_launch(void* const* d_in, const int* in_sizes, int n_in,
                              void* d_out, int out_size) {
    const float* x        = (const float*)d_in[0];
    const int*   clusters = (const int*)  d_in[1];
    const float* enc_w    = (const float*)d_in[2];
    const float* enc_b    = (const float*)d_in[3];
    const float* dec_w    = (const float*)d_in[4];
    const float* dec_b    = (const float*)d_in[5];
    float*       y        = (float*)d_out;

    static int smem_set = 0;
    const int smem_bytes = RROWS * TSTRIDE * sizeof(float);  // 132096
    if (!smem_set) {
        cudaFuncSetAttribute(ensemble_kernel,
                             cudaFuncAttributeMaxDynamicSharedMemorySize, smem_bytes);
        smem_set = 1;
    }

    prep_kernel<<<32, 512>>>(enc_w, enc_b, dec_w, dec_b, clusters);
    ensemble_kernel<<<BATCH / RROWS, THREADS, smem_bytes>>>(x, y);
}

// round 9
// speedup vs baseline: 1.2210x; 1.2210x over previous
#include <cuda_runtime.h>
#include <cstdint>

#define NC     16      // clusters
#define CS     32      // cluster size
#define NH     16      // hidden
#define NF     512     // features = NC*CS
#define BATCH  131072
#define RROWS  64      // rows per block tile
#define THREADS 256
#define TSTRIDE 516    // padded row stride (floats): conflict-free rotation scheme

// Fused per-cluster weights: W[n][c][k] = sum_h dec_w[n][c][h]*enc_w[n][h][k]
__device__ float g_W[NC * CS * CS];
__device__ float g_bias[NC * CS];
__device__ int   g_pos[NF];   // pos[feature] = n*32+k  (inverse of clusters perm)

__global__ void prep_kernel(const float* __restrict__ enc_w,
                            const float* __restrict__ enc_b,
                            const float* __restrict__ dec_w,
                            const float* __restrict__ dec_b,
                            const int*   __restrict__ clusters) {
    int t = blockIdx.x * blockDim.x + threadIdx.x;
    if (t < NC * CS * CS) {
        int n = t >> 10;
        int c = (t >> 5) & 31;
        int k = t & 31;
        const float* dw = dec_w + (n * CS + c) * NH;
        const float* ew = enc_w + n * NH * CS + k;
        float s = 0.f;
#pragma unroll
        for (int h = 0; h < NH; h++) s += dw[h] * ew[h * CS];
        g_W[t] = s;
    }
    if (t < NC * CS) {
        int n = t >> 5;
        const float* dw = dec_w + t * NH;
        const float* eb = enc_b + n * NH;
        float s = dec_b[t];
#pragma unroll
        for (int h = 0; h < NH; h++) s += dw[h] * eb[h];
        g_bias[t] = s;
        g_pos[clusters[t]] = t;
    }
}

// P=4 scheme (R7) + dual-row ILP + software-pipelined LDS.
// Warp = cluster (2 clusters sequentially). Lane = rg*8+q:
//   rg in 0..3 = row slot, q in 0..7 = output quad (outputs 4q..4q+3).
// Each lane processes rows (it*8+rg) and (it*8+rg+4) per step with 8
// accumulator chains; reads each row's 128B segment as 8 rotated 16B chunks
// (all 32 lane addresses distinct & bank-conflict-free, stride 516).
__global__ void __launch_bounds__(THREADS, 1)
ensemble_kernel(const float* __restrict__ x, float* __restrict__ y) {
    extern __shared__ __align__(16) float tile[];   // RROWS * TSTRIDE floats

    const int tid  = threadIdx.x;
    const int warp = tid >> 5;       // 0..7
    const int lane = tid & 31;
    const int rg   = lane >> 3;      // 0..3
    const int q    = lane & 7;       // 0..7
    const long long row0 = (long long)blockIdx.x * RROWS;

    // ---- load phase: coalesced global read, permuted scatter into smem ----
    {
        const float4* xv = (const float4*)(x) + row0 * (NF / 4);
        const int4*   pv = (const int4*)g_pos;
#pragma unroll 4
        for (int i = 0; i < (RROWS * NF / 4) / THREADS; i++) {
            int idx = tid + i * THREADS;  // float4 index within tile
            int r   = idx >> 7;           // 128 float4 per row
            int f4  = idx & 127;
            float4 v = xv[idx];
            int4   p = pv[f4];
            float* dst = tile + r * TSTRIDE;
            dst[p.x] = v.x;
            dst[p.y] = v.y;
            dst[p.z] = v.z;
            dst[p.w] = v.w;
        }
    }
    __syncthreads();

    uint32_t sb;
    asm("{ .reg .u64 t0; cvta.to.shared.u64 t0, %1; cvt.u32.u64 %0, t0; }"
        : "=r"(sb) : "l"(tile));

    // ---- compute phase: 2 clusters per warp, W register-stationary ----
#pragma unroll 1
    for (int half = 0; half < 2; half++) {
        const int cl = warp + half * 8;

        // This lane's 4 weight rows, chunk-rotated by q so offsets are static.
        // w[o][2j], w[o][2j+1] = W[cl][4q+o][ch*4 .. ch*4+3], ch = (q+j)&7.
        unsigned long long w[4][16];
#pragma unroll
        for (int o = 0; o < 4; o++) {
            const float* wr = g_W + (cl * CS + 4 * q + o) * CS;
#pragma unroll
            for (int j = 0; j < 8; j++) {
                int ch = (q + j) & 7;
                ulonglong2 v = *(const ulonglong2*)(wr + ch * 4);
                w[o][2 * j]     = v.x;
                w[o][2 * j + 1] = v.y;
            }
        }
        const float4 bias = *(const float4*)(g_bias + cl * CS + 4 * q);

        const uint32_t seg = (uint32_t)(cl * CS * 4);
        float* ybase = y + row0 * NF + cl * CS + q * 4;

#pragma unroll 1
        for (int it = 0; it < RROWS / 8; it++) {
            const int rA = it * 8 + rg;          // row A
            const int rB = rA + 4;               // row B
            const uint32_t baseA = sb + (uint32_t)(rA * TSTRIDE * 4) + seg;
            const uint32_t baseB = baseA + (uint32_t)(4 * TSTRIDE * 4);

            unsigned long long xA0, xA1, xB0, xB1;
            unsigned long long nA0, nA1, nB0, nB1;

            // prologue: load chunk j=0 for both rows
            {
                uint32_t off = (uint32_t)(q << 4);
                asm volatile("ld.shared.v2.u64 {%0,%1},[%2];"
                             : "=l"(xA0), "=l"(xA1) : "r"(baseA + off));
                asm volatile("ld.shared.v2.u64 {%0,%1},[%2];"
                             : "=l"(xB0), "=l"(xB1) : "r"(baseB + off));
            }

            unsigned long long a0, a1, a2, a3, b0, b1, b2, b3;
#pragma unroll
            for (int j = 0; j < 8; j++) {
                if (j < 7) {  // prefetch next chunk while computing this one
                    uint32_t off = (uint32_t)(((q + j + 1) & 7) << 4);
                    asm volatile("ld.shared.v2.u64 {%0,%1},[%2];"
                                 : "=l"(nA0), "=l"(nA1) : "r"(baseA + off));
                    asm volatile("ld.shared.v2.u64 {%0,%1},[%2];"
                                 : "=l"(nB0), "=l"(nB1) : "r"(baseB + off));
                }
                if (j == 0) {
                    asm("mul.rn.f32x2 %0,%1,%2;" : "=l"(a0) : "l"(w[0][0]), "l"(xA0));
                    asm("mul.rn.f32x2 %0,%1,%2;" : "=l"(a1) : "l"(w[1][0]), "l"(xA0));
                    asm("mul.rn.f32x2 %0,%1,%2;" : "=l"(a2) : "l"(w[2][0]), "l"(xA0));
                    asm("mul.rn.f32x2 %0,%1,%2;" : "=l"(a3) : "l"(w[3][0]), "l"(xA0));
                    asm("mul.rn.f32x2 %0,%1,%2;" : "=l"(b0) : "l"(w[0][0]), "l"(xB0));
                    asm("mul.rn.f32x2 %0,%1,%2;" : "=l"(b1) : "l"(w[1][0]), "l"(xB0));
                    asm("mul.rn.f32x2 %0,%1,%2;" : "=l"(b2) : "l"(w[2][0]), "l"(xB0));
                    asm("mul.rn.f32x2 %0,%1,%2;" : "=l"(b3) : "l"(w[3][0]), "l"(xB0));
                } else {
                    asm("fma.rn.f32x2 %0,%1,%2,%0;" : "+l"(a0) : "l"(w[0][2 * j]), "l"(xA0));
                    asm("fma.rn.f32x2 %0,%1,%2,%0;" : "+l"(a1) : "l"(w[1][2 * j]), "l"(xA0));
                    asm("fma.rn.f32x2 %0,%1,%2,%0;" : "+l"(a2) : "l"(w[2][2 * j]), "l"(xA0));
                    asm("fma.rn.f32x2 %0,%1,%2,%0;" : "+l"(a3) : "l"(w[3][2 * j]), "l"(xA0));
                    asm("fma.rn.f32x2 %0,%1,%2,%0;" : "+l"(b0) : "l"(w[0][2 * j]), "l"(xB0));
                    asm("fma.rn.f32x2 %0,%1,%2,%0;" : "+l"(b1) : "l"(w[1][2 * j]), "l"(xB0));
                    asm("fma.rn.f32x2 %0,%1,%2,%0;" : "+l"(b2) : "l"(w[2][2 * j]), "l"(xB0));
                    asm("fma.rn.f32x2 %0,%1,%2,%0;" : "+l"(b3) : "l"(w[3][2 * j]), "l"(xB0));
                }
                asm("fma.rn.f32x2 %0,%1,%2,%0;" : "+l"(a0) : "l"(w[0][2 * j + 1]), "l"(xA1));
                asm("fma.rn.f32x2 %0,%1,%2,%0;" : "+l"(a1) : "l"(w[1][2 * j + 1]), "l"(xA1));
                asm("fma.rn.f32x2 %0,%1,%2,%0;" : "+l"(a2) : "l"(w[2][2 * j + 1]), "l"(xA1));
                asm("fma.rn.f32x2 %0,%1,%2,%0;" : "+l"(a3) : "l"(w[3][2 * j + 1]), "l"(xA1));
                asm("fma.rn.f32x2 %0,%1,%2,%0;" : "+l"(b0) : "l"(w[0][2 * j + 1]), "l"(xB1));
                asm("fma.rn.f32x2 %0,%1,%2,%0;" : "+l"(b1) : "l"(w[1][2 * j + 1]), "l"(xB1));
                asm("fma.rn.f32x2 %0,%1,%2,%0;" : "+l"(b2) : "l"(w[2][2 * j + 1]), "l"(xB1));
                asm("fma.rn.f32x2 %0,%1,%2,%0;" : "+l"(b3) : "l"(w[3][2 * j + 1]), "l"(xB1));

                xA0 = nA0; xA1 = nA1; xB0 = nB0; xB1 = nB1;
            }

            uint32_t lo, hi;
            float4 outA, outB;
            asm("mov.b64 {%0,%1},%2;" : "=r"(lo), "=r"(hi) : "l"(a0));
            outA.x = __uint_as_float(lo) + __uint_as_float(hi) + bias.x;
            asm("mov.b64 {%0,%1},%2;" : "=r"(lo), "=r"(hi) : "l"(a1));
            outA.y = __uint_as_float(lo) + __uint_as_float(hi) + bias.y;
            asm("mov.b64 {%0,%1},%2;" : "=r"(lo), "=r"(hi) : "l"(a2));
            outA.z = __uint_as_float(lo) + __uint_as_float(hi) + bias.z;
            asm("mov.b64 {%0,%1},%2;" : "=r"(lo), "=r"(hi) : "l"(a3));
            outA.w = __uint_as_float(lo) + __uint_as_float(hi) + bias.w;
            asm("mov.b64 {%0,%1},%2;" : "=r"(lo), "=r"(hi) : "l"(b0));
            outB.x = __uint_as_float(lo) + __uint_as_float(hi) + bias.x;
            asm("mov.b64 {%0,%1},%2;" : "=r"(lo), "=r"(hi) : "l"(b1));
            outB.y = __uint_as_float(lo) + __uint_as_float(hi) + bias.y;
            asm("mov.b64 {%0,%1},%2;" : "=r"(lo), "=r"(hi) : "l"(b2));
            outB.z = __uint_as_float(lo) + __uint_as_float(hi) + bias.z;
            asm("mov.b64 {%0,%1},%2;" : "=r"(lo), "=r"(hi) : "l"(b3));
            outB.w = __uint_as_float(lo) + __uint_as_float(hi) + bias.w;

            *(float4*)(ybase + (size_t)rA * NF) = outA;
            *(float4*)(ybase + (size_t)rB * NF) = outB;
        }
        // no __syncthreads needed between halves: tile is read-only here
    }
}

extern "C" void kernel_launch(void* const* d_in, const int* in_sizes, int n_in,
                              void* d_out, int out_size) {
    const float* x        = (const float*)d_in[0];
    const int*   clusters = (const int*)  d_in[1];
    const float* enc_w    = (const float*)d_in[2];
    const float* enc_b    = (const float*)d_in[3];
    const float* dec_w    = (const float*)d_in[4];
    const float* dec_b    = (const float*)d_in[5];
    float*       y        = (float*)d_out;

    static int smem_set = 0;
    const int smem_bytes = RROWS * TSTRIDE * sizeof(float);  // 132096
    if (!smem_set) {
        cudaFuncSetAttribute(ensemble_kernel,
                             cudaFuncAttributeMaxDynamicSharedMemorySize, smem_bytes);
        smem_set = 1;
    }

    prep_kernel<<<32, 512>>>(enc_w, enc_b, dec_w, dec_b, clusters);
    ensemble_kernel<<<BATCH / RROWS, THREADS, smem_bytes>>>(x, y);
}